// round 6
// baseline (speedup 1.0000x reference)
#include <cuda_runtime.h>
#include <cstdint>

// SimpleSparseConvNet: rulebook sparse conv, Cin=1, Cout=16.
// Quad-lane degree-aware scatter, 4 pairs per quad-thread (front-batched loads
// for MLP). Byte-packed degree counts (deg <= 27), zeroed via memset node.
// deg==1 rows: plain STG.128 (no memset of output). deg>=2: zero + red.v4.

#define MAX_NOUT (4 * 1024 * 1024)

__device__ __align__(16) unsigned char g_counts[MAX_NOUT];

__device__ __forceinline__ void red_add_v4(float* addr, float a, float b, float c, float d) {
    asm volatile("red.global.add.v4.f32 [%0], {%1, %2, %3, %4};"
                 :: "l"(addr), "f"(a), "f"(b), "f"(c), "f"(d)
                 : "memory");
}

// ---- K1: byte-packed histogram of out_idx ------------------------------------
__global__ void __launch_bounds__(256)
k_count(const int* __restrict__ out_idx, int M) {
    int m = blockIdx.x * blockDim.x + threadIdx.x;
    if (m < M) {
        int o = out_idx[m];
        atomicAdd(reinterpret_cast<unsigned int*>(g_counts) + (o >> 2),
                  1u << ((o & 3) * 8));
    }
}

// ---- K2: zero output rows with deg >= 2 (thread per float4, coalesced) ------
__global__ void __launch_bounds__(256)
k_zero_multi(float* __restrict__ out, int n_out) {
    int tid = blockIdx.x * blockDim.x + threadIdx.x;
    int o = tid >> 2;
    if (o >= n_out) return;
    if (__ldg(&g_counts[o]) >= 2u) {
        reinterpret_cast<float4*>(out)[tid] = make_float4(0.f, 0.f, 0.f, 0.f);
    }
}

// ---- K3: scatter, 4 lanes per pair, 4 pairs per quad --------------------------
__global__ void __launch_bounds__(256)
k_scatter(const float* __restrict__ feats,
          const float* __restrict__ weight,
          const int* __restrict__ in_idx,
          const int* __restrict__ out_idx,
          const int* __restrict__ k_idx,
          float* __restrict__ out,
          int M, int Q) {
    int tid = blockIdx.x * blockDim.x + threadIdx.x;
    int q = tid >> 2;
    int j = tid & 3;
    if (q >= Q) return;

    int   o[4], k[4], ii[4];
    bool  vl[4];
    float f[4];
    unsigned int d[4];
    float4 w[4];

    // ---- front-batched independent index loads (maximize MLP) ----
#pragma unroll
    for (int r = 0; r < 4; r++) {
        int m = q + r * Q;
        vl[r] = (m < M);
        if (vl[r]) {
            o[r]  = __ldg(&out_idx[m]);
            k[r]  = __ldg(&k_idx[m]);
            ii[r] = __ldg(&in_idx[m]);
        }
    }
    // ---- dependent loads, still batched across the 4 pairs ----
#pragma unroll
    for (int r = 0; r < 4; r++) {
        if (vl[r]) {
            f[r] = __ldg(&feats[ii[r]]);
            d[r] = __ldg(&g_counts[o[r]]);
            w[r] = __ldg(reinterpret_cast<const float4*>(weight) + (size_t)k[r] * 4 + j);
        }
    }
    // ---- emit ----
#pragma unroll
    for (int r = 0; r < 4; r++) {
        if (vl[r]) {
            float4 v = make_float4(f[r] * w[r].x, f[r] * w[r].y,
                                   f[r] * w[r].z, f[r] * w[r].w);
            float* op = out + (size_t)o[r] * 16 + j * 4;
            if (d[r] == 1u) *reinterpret_cast<float4*>(op) = v;
            else            red_add_v4(op, v.x, v.y, v.z, v.w);
        }
    }
}

extern "C" void kernel_launch(void* const* d_in, const int* in_sizes, int n_in,
                              void* d_out, int out_size) {
    const float* feats  = (const float*)d_in[0];
    const float* weight = (const float*)d_in[1];
    const int* in_idx   = (const int*)d_in[2];
    const int* out_idx  = (const int*)d_in[3];
    const int* k_idx    = (const int*)d_in[4];
    float* out = (float*)d_out;

    const int M = in_sizes[2];
    const int n_out = out_size / 16;
    const int Q = (M + 3) / 4;          // quads of 4 pairs

    void* counts_ptr = nullptr;
    cudaGetSymbolAddress(&counts_ptr, g_counts);

    const int T = 256;
    // zero byte-counts via DMA memset node (pad to word boundary)
    cudaMemsetAsync(counts_ptr, 0, (size_t)((n_out + 3) & ~3), 0);
    k_count<<<(M + T - 1) / T, T>>>(out_idx, M);
    k_zero_multi<<<((size_t)n_out * 4 + T - 1) / T, T>>>(out, n_out);
    k_scatter<<<((size_t)Q * 4 + T - 1) / T, T>>>(feats, weight, in_idx, out_idx,
                                                  k_idx, out, M, Q);
}

// round 7
// speedup vs baseline: 1.1568x; 1.1568x over previous
#include <cuda_runtime.h>
#include <cstdint>

// SimpleSparseConvNet: rulebook sparse conv, Cin=1, Cout=16.
// Quad-lane degree-aware scatter, 4 pairs per quad-thread, branch-free loads.
// Word degree counts (memset-zeroed). deg==1 rows: plain STG.128 (no output
// memset). deg>=2 rows: zeroed, then red.global.add.v4.f32.

#define MAX_NOUT (4 * 1024 * 1024)

__device__ __align__(16) unsigned int g_counts[MAX_NOUT];

__device__ __forceinline__ void red_add_v4(float* addr, float a, float b, float c, float d) {
    asm volatile("red.global.add.v4.f32 [%0], {%1, %2, %3, %4};"
                 :: "l"(addr), "f"(a), "f"(b), "f"(c), "f"(d)
                 : "memory");
}

// ---- K1: histogram of out_idx -----------------------------------------------
__global__ void __launch_bounds__(256)
k_count(const int* __restrict__ out_idx, int M) {
    int m = blockIdx.x * blockDim.x + threadIdx.x;
    if (m < M) atomicAdd(&g_counts[out_idx[m]], 1u);
}

// ---- K2: zero output rows with deg >= 2 (thread per float4, coalesced) ------
__global__ void __launch_bounds__(256)
k_zero_multi(float* __restrict__ out, int n_out) {
    int tid = blockIdx.x * blockDim.x + threadIdx.x;
    int o = tid >> 2;
    if (o >= n_out) return;
    if (__ldg(&g_counts[o]) >= 2u) {
        reinterpret_cast<float4*>(out)[tid] = make_float4(0.f, 0.f, 0.f, 0.f);
    }
}

// ---- K3: scatter, 4 lanes per pair, 4 pairs per quad, branch-free loads ------
__global__ void __launch_bounds__(256)
k_scatter(const float* __restrict__ feats,
          const float* __restrict__ weight,
          const int* __restrict__ in_idx,
          const int* __restrict__ out_idx,
          const int* __restrict__ k_idx,
          float* __restrict__ out,
          int M, int Q) {
    int tid = blockIdx.x * blockDim.x + threadIdx.x;
    int q = tid >> 2;
    int j = tid & 3;
    if (q >= Q) return;

    // Streams 0..2 always valid for q < Q (M >= 3Q-1). Stream 3 clamped.
    const int m3 = q + 3 * Q;
    const bool v3 = (m3 < M);
    int m[4] = { q, q + Q, q + 2 * Q, v3 ? m3 : (M - 1) };

    // ---- unconditional front-batched index loads (max MLP, no branches) ----
    int o[4], k[4], ii[4];
#pragma unroll
    for (int r = 0; r < 4; r++) {
        o[r]  = __ldg(&out_idx[m[r]]);
        k[r]  = __ldg(&k_idx[m[r]]);
        ii[r] = __ldg(&in_idx[m[r]]);
    }
    // ---- dependent loads, batched ----
    float f[4];
    unsigned int d[4];
    float4 w[4];
#pragma unroll
    for (int r = 0; r < 4; r++) {
        f[r] = __ldg(&feats[ii[r]]);
        d[r] = __ldg(&g_counts[o[r]]);
        w[r] = __ldg(reinterpret_cast<const float4*>(weight) + (size_t)k[r] * 4 + j);
    }
    // ---- emit (only stream 3 predicated) ----
#pragma unroll
    for (int r = 0; r < 4; r++) {
        if (r == 3 && !v3) break;
        float4 v = make_float4(f[r] * w[r].x, f[r] * w[r].y,
                               f[r] * w[r].z, f[r] * w[r].w);
        float* op = out + (size_t)o[r] * 16 + j * 4;
        if (d[r] == 1u) *reinterpret_cast<float4*>(op) = v;
        else            red_add_v4(op, v.x, v.y, v.z, v.w);
    }
}

extern "C" void kernel_launch(void* const* d_in, const int* in_sizes, int n_in,
                              void* d_out, int out_size) {
    const float* feats  = (const float*)d_in[0];
    const float* weight = (const float*)d_in[1];
    const int* in_idx   = (const int*)d_in[2];
    const int* out_idx  = (const int*)d_in[3];
    const int* k_idx    = (const int*)d_in[4];
    float* out = (float*)d_out;

    const int M = in_sizes[2];
    const int n_out = out_size / 16;
    const int Q = (M + 3) / 4;

    void* counts_ptr = nullptr;
    cudaGetSymbolAddress(&counts_ptr, g_counts);

    const int T = 256;
    cudaMemsetAsync(counts_ptr, 0, (size_t)n_out * sizeof(unsigned int), 0);
    k_count<<<(M + T - 1) / T, T>>>(out_idx, M);
    k_zero_multi<<<((size_t)n_out * 4 + T - 1) / T, T>>>(out, n_out);
    k_scatter<<<((size_t)Q * 4 + T - 1) / T, T>>>(feats, weight, in_idx, out_idx,
                                                  k_idx, out, M, Q);
}